// round 2
// baseline (speedup 1.0000x reference)
#include <cuda_runtime.h>
#include <cstdint>

#define BB 32
#define TT 8
#define NN 512
#define FF 4
#define HH 64
#define CCO 12

// ---------------- scratch (static device globals; no allocation) -------------
__device__ float g_Wx[BB * TT * NN * HH];      // 8,388,608 floats
__device__ float g_asrc[BB * TT * NN];         // 131,072
__device__ float g_adst[BB * TT * NN];
__device__ float g_gat[BB * TT * NN * HH];     // 8,388,608
__device__ float g_gates[BB * NN * TT * 12];   // 1,572,864
__device__ float g_gru[BB * NN * TT * FF];     // 524,288

// ---------------- fast exp on the FMA/ALU pipes (no MUFU, no F2I) ------------
// exp(x) = 2^(x*log2e). Integer part via magic-number round-to-nearest,
// fraction f in [-0.5, 0.5], 2^f by degree-5 Taylor (rel err ~2e-6).
__device__ __forceinline__ float fexp(float x) {
    float t = x * 1.4426950408889634f;
    t = fminf(fmaxf(t, -30.f), 30.f);
    float r  = t + 12582912.f;                    // 1.5 * 2^23: RN to integer
    int   e  = __float_as_int(r) - 0x4B400000;    // integer part as int
    float fl = r - 12582912.f;
    float f  = t - fl;                            // [-0.5, 0.5]
    const float c1 = 0.6931471805599453f;
    const float c2 = 0.2402265069591007f;
    const float c3 = 0.05550410866482158f;
    const float c4 = 0.009618129107628477f;
    const float c5 = 0.0013333558146428443f;
    float p = 1.f + f * (c1 + f * (c2 + f * (c3 + f * (c4 + f * c5))));
    float s = __int_as_float((e + 127) << 23);
    return p * s;
}

__device__ __forceinline__ float fsigmoid(float x) {
    return 1.f / (1.f + fexp(-x));
}
__device__ __forceinline__ float ftanh(float x) {
    float e = fexp(2.f * x);
    return (e - 1.f) / (e + 1.f);
}

// ---------------- K1: Wx = x @ gat_W ; a_src, a_dst --------------------------
// one warp per (b,t,n) row; lane handles h and h+32.
__global__ void k_wx(const float* __restrict__ x, const float* __restrict__ W,
                     const float* __restrict__ att_src, const float* __restrict__ att_dst) {
    int warp = (blockIdx.x * blockDim.x + threadIdx.x) >> 5;
    int lane = threadIdx.x & 31;
    if (warp >= BB * TT * NN) return;
    const float* xr = x + warp * 4;
    float x0 = xr[0], x1 = xr[1], x2 = xr[2], x3 = xr[3];
    int h0 = lane, h1 = lane + 32;
    float w0 = x0 * W[h0] + x1 * W[64 + h0] + x2 * W[128 + h0] + x3 * W[192 + h0];
    float w1 = x0 * W[h1] + x1 * W[64 + h1] + x2 * W[128 + h1] + x3 * W[192 + h1];
    g_Wx[(size_t)warp * 64 + h0] = w0;
    g_Wx[(size_t)warp * 64 + h1] = w1;
    float ps = w0 * att_src[h0] + w1 * att_src[h1];
    float pd = w0 * att_dst[h0] + w1 * att_dst[h1];
#pragma unroll
    for (int o = 16; o; o >>= 1) {
        ps += __shfl_xor_sync(0xFFFFFFFFu, ps, o);
        pd += __shfl_xor_sync(0xFFFFFFFFu, pd, o);
    }
    if (lane == 0) { g_asrc[warp] = ps; g_adst[warp] = pd; }
}

// ---------------- K2: fused GAT softmax + aggregate --------------------------
// grid (N/128, B*T), 256 threads. Thread pair (2 per i-row) owns 32 h each.
// Accumulation in packed fp32x2 (FFMA2) — halves fma-pipe issue slots.
#define TI 128
#define TJ 32

union F4U2 { float4 f4; unsigned long long u2[2]; };

__global__ __launch_bounds__(256) void k_att(const float* __restrict__ adj,
                                             const float* __restrict__ bias) {
    __shared__ __align__(16) float s_adj[TJ][TI];
    __shared__ __align__(16) float s_wx[TJ][HH];
    __shared__ float s_asrc[TJ];

    int bt  = blockIdx.y;
    int i0  = blockIdx.x * TI;
    int tid = threadIdx.x;
    int il  = tid >> 1;
    int hb  = (tid & 1) * 32;
    int ig  = i0 + il;

    float adst = g_adst[bt * NN + ig];
    const float* adjbt = adj + (size_t)bt * NN * NN;
    const float* wxbt  = g_Wx + (size_t)bt * NN * HH;
    const float* asbt  = g_asrc + bt * NN;

    unsigned long long acc2[16];
#pragma unroll
    for (int k = 0; k < 16; k++) acc2[k] = 0ULL;
    float denom = 0.f;

    for (int j0 = 0; j0 < NN; j0 += TJ) {
        __syncthreads();
        // adj tile: 32 x 128 floats, coalesced float4
#pragma unroll
        for (int u = 0; u < 4; u++) {
            int idx = tid + u * 256;           // 0..1023
            int jr  = idx >> 5;
            int cc  = (idx & 31) * 4;
            float4 v = *(const float4*)&adjbt[(size_t)(j0 + jr) * NN + i0 + cc];
            *(float4*)&s_adj[jr][cc] = v;
        }
        // Wx tile: 32 x 64 floats
#pragma unroll
        for (int u = 0; u < 2; u++) {
            int idx = tid + u * 256;           // 0..511
            int jr  = idx >> 4;
            int cc  = (idx & 15) * 4;
            float4 v = *(const float4*)&wxbt[(size_t)(j0 + jr) * HH + cc];
            *(float4*)&s_wx[jr][cc] = v;
        }
        if (tid < TJ) s_asrc[tid] = asbt[j0 + tid];
        __syncthreads();

#pragma unroll 4
        for (int j = 0; j < TJ; j++) {
            float v = adst + s_asrc[j];
            float e = v > 0.f ? v : 0.2f * v;          // leaky_relu 0.2
            float a = s_adj[j][il];
            bool  m = (a != 0.f) || ((j0 + j) == ig);  // adj^T nonzero OR eye
            float p = m ? fexp(e) : 0.f;
            denom += p;
            unsigned long long pp;
            asm("mov.b64 %0, {%1, %1};" : "=l"(pp) : "f"(p));
#pragma unroll
            for (int k4 = 0; k4 < 8; k4++) {
                F4U2 w;
                w.f4 = *(const float4*)&s_wx[j][hb + k4 * 4];
                asm("fma.rn.f32x2 %0, %1, %2, %0;"
                    : "+l"(acc2[k4 * 2])     : "l"(pp), "l"(w.u2[0]));
                asm("fma.rn.f32x2 %0, %1, %2, %0;"
                    : "+l"(acc2[k4 * 2 + 1]) : "l"(pp), "l"(w.u2[1]));
            }
        }
    }

    float rinv = 1.f / denom;
    float* out = g_gat + ((size_t)bt * NN + ig) * HH + hb;
#pragma unroll
    for (int k = 0; k < 16; k++) {
        float lo, hi;
        asm("mov.b64 {%0, %1}, %2;" : "=f"(lo), "=f"(hi) : "l"(acc2[k]));
        out[k * 2]     = lo * rinv + bias[hb + k * 2];
        out[k * 2 + 1] = hi * rinv + bias[hb + k * 2 + 1];
    }
}

// ---------------- K3: GRU input gates: seq @ W_ih^T + b_ih -------------------
// one thread per flat row (131072 rows of 64), 12 gate outputs each.
__global__ void k_gates(const float* __restrict__ Wih, const float* __restrict__ bih) {
    __shared__ float sW[12 * 64];
    __shared__ float sb[12];
    for (int i = threadIdx.x; i < 768; i += blockDim.x) sW[i] = Wih[i];
    if (threadIdx.x < 12) sb[threadIdx.x] = bih[threadIdx.x];
    __syncthreads();
    int r = blockIdx.x * blockDim.x + threadIdx.x;
    if (r >= BB * NN * TT) return;
    const float* in = g_gat + (size_t)r * 64;
    float acc[12];
#pragma unroll
    for (int g = 0; g < 12; g++) acc[g] = sb[g];
#pragma unroll
    for (int h4 = 0; h4 < 16; h4++) {
        float4 v = *(const float4*)&in[h4 * 4];
#pragma unroll
        for (int g = 0; g < 12; g++) {
            const float* w = &sW[g * 64 + h4 * 4];
            acc[g] += v.x * w[0] + v.y * w[1] + v.z * w[2] + v.w * w[3];
        }
    }
    float* o = g_gates + (size_t)r * 12;
#pragma unroll
    for (int g = 0; g < 12; g++) o[g] = acc[g];
}

// ---------------- K4: GRU recurrence (hidden=4, T=8) -------------------------
// one thread per sequence q (B*N = 16384)
__global__ void k_gru(const float* __restrict__ Whh, const float* __restrict__ bhh) {
    int q = blockIdx.x * blockDim.x + threadIdx.x;
    if (q >= BB * NN) return;
    float Wl[48];
#pragma unroll
    for (int i = 0; i < 48; i++) Wl[i] = Whh[i];
    float bl[12];
#pragma unroll
    for (int i = 0; i < 12; i++) bl[i] = bhh[i];

    float h[4] = {0.f, 0.f, 0.f, 0.f};
    for (int s = 0; s < 8; s++) {
        const float* gx = g_gates + (size_t)(q * 8 + s) * 12;
        float gxr[12];
#pragma unroll
        for (int i = 0; i < 12; i++) gxr[i] = gx[i];
        float gh[12];
#pragma unroll
        for (int g = 0; g < 12; g++) {
            gh[g] = bl[g] + h[0] * Wl[g * 4 + 0] + h[1] * Wl[g * 4 + 1]
                          + h[2] * Wl[g * 4 + 2] + h[3] * Wl[g * 4 + 3];
        }
        float hn[4];
#pragma unroll
        for (int f = 0; f < 4; f++) {
            float r  = fsigmoid(gxr[f]     + gh[f]);
            float z  = fsigmoid(gxr[4 + f] + gh[4 + f]);
            float nc = ftanh(gxr[8 + f] + r * gh[8 + f]);
            hn[f] = (1.f - z) * nc + z * h[f];
        }
#pragma unroll
        for (int f = 0; f < 4; f++) {
            h[f] = hn[f];
            g_gru[(size_t)(q * 8 + s) * 4 + f] = h[f];
        }
    }
}

// ---------------- K5: Conv2d(T=8 -> 12, 3x3, SAME over (N,4)) + Linear(4->2) -
// grid (N/128, B), 128 threads (one per n)
__global__ void k_conv(const float* __restrict__ cW, const float* __restrict__ cb,
                       const float* __restrict__ oW, const float* __restrict__ ob,
                       float* __restrict__ out) {
    __shared__ float sg[130][33];   // [n_local+1][t*4+f], stride 33 = conflict-free
    __shared__ float sw[CCO * TT * 9];
    __shared__ float sow[8], sob[2], scb[CCO];

    int b   = blockIdx.y;
    int n0  = blockIdx.x * 128;
    int tid = threadIdx.x;

    for (int i = tid; i < CCO * TT * 9; i += 128) sw[i] = cW[i];
    if (tid < 8)   sow[tid] = oW[tid];
    if (tid < 2)   sob[tid] = ob[tid];
    if (tid < CCO) scb[tid] = cb[tid];

    for (int i = tid; i < 130 * 32; i += 128) {
        int nl = i >> 5;
        int c  = i & 31;
        int n  = n0 + nl - 1;
        float v = 0.f;
        if (n >= 0 && n < NN)
            v = g_gru[(((size_t)b * NN + n) * TT) * FF + c];
        sg[nl][c] = v;
    }
    __syncthreads();

    int nl = tid;  // global n = n0 + nl; smem center row = nl + 1
    for (int co = 0; co < CCO; co++) {
        float y0 = scb[co], y1 = scb[co], y2 = scb[co], y3 = scb[co];
#pragma unroll
        for (int ci = 0; ci < TT; ci++) {
#pragma unroll
            for (int kh = 0; kh < 3; kh++) {
                const float* row = &sg[nl + kh][ci * 4];
                float r0 = row[0], r1 = row[1], r2 = row[2], r3 = row[3];
                const float* w = &sw[(co * TT + ci) * 9 + kh * 3];
                float w0 = w[0], w1 = w[1], w2 = w[2];
                y0 += w1 * r0 + w2 * r1;
                y1 += w0 * r0 + w1 * r1 + w2 * r2;
                y2 += w0 * r1 + w1 * r2 + w2 * r3;
                y3 += w0 * r2 + w1 * r3;
            }
        }
        float o0 = sob[0] + y0 * sow[0] + y1 * sow[1] + y2 * sow[2] + y3 * sow[3];
        float o1 = sob[1] + y0 * sow[4] + y1 * sow[5] + y2 * sow[6] + y3 * sow[7];
        size_t oi = (((size_t)b * CCO + co) * NN + (n0 + nl)) * 2;
        out[oi]     = o0;
        out[oi + 1] = o1;
    }
}

// -----------------------------------------------------------------------------
extern "C" void kernel_launch(void* const* d_in, const int* in_sizes, int n_in,
                              void* d_out, int out_size) {
    const float* x        = (const float*)d_in[0];
    const float* adj      = (const float*)d_in[1];
    const float* gat_W    = (const float*)d_in[2];
    const float* att_src  = (const float*)d_in[3];
    const float* att_dst  = (const float*)d_in[4];
    const float* gat_bias = (const float*)d_in[5];
    const float* gru_Wih  = (const float*)d_in[6];
    const float* gru_Whh  = (const float*)d_in[7];
    const float* gru_bih  = (const float*)d_in[8];
    const float* gru_bhh  = (const float*)d_in[9];
    const float* conv_W   = (const float*)d_in[10];
    const float* conv_b   = (const float*)d_in[11];
    const float* out_W    = (const float*)d_in[12];
    const float* out_b    = (const float*)d_in[13];
    float* out = (float*)d_out;

    // K1: Wx + attention logits. one warp per row, 8 rows/block.
    k_wx<<<(BB * TT * NN) / 8, 256>>>(x, gat_W, att_src, att_dst);

    // K2: fused attention
    dim3 g2(NN / TI, BB * TT);
    k_att<<<g2, 256>>>(adj, gat_bias);

    // K3: gates
    k_gates<<<(BB * NN * TT) / 256, 256>>>(gru_Wih, gru_bih);

    // K4: recurrence
    k_gru<<<(BB * NN) / 256, 256>>>(gru_Whh, gru_bhh);

    // K5: conv + linear
    dim3 g5(NN / 128, BB);
    k_conv<<<g5, 128>>>(conv_W, conv_b, out_W, out_b, out);
}

// round 3
// speedup vs baseline: 1.4345x; 1.4345x over previous
#include <cuda_runtime.h>
#include <cstdint>

#define BB 32
#define TT 8
#define NN 512
#define FF 4
#define HH 64
#define CCO 12

// ---------------- scratch (static device globals; no allocation) -------------
__device__ float g_Wx[BB * TT * NN * HH];      // 8,388,608 floats
__device__ float g_asrc[BB * TT * NN];         // 131,072
__device__ float g_adst[BB * TT * NN];
__device__ float g_gat[BB * TT * NN * HH];     // 8,388,608
__device__ float g_gates[BB * NN * TT * 12];   // 1,572,864
__device__ float g_gru[BB * NN * TT * FF];     // 524,288

// fast exp for GRU nonlinearities (small volume)
__device__ __forceinline__ float fsigmoid(float x) { return 1.f / (1.f + __expf(-x)); }
__device__ __forceinline__ float ftanh(float x)    { return tanhf(x); }

// ---------------- K1: Wx = x @ gat_W ; a_src, a_dst --------------------------
__global__ void k_wx(const float* __restrict__ x, const float* __restrict__ W,
                     const float* __restrict__ att_src, const float* __restrict__ att_dst) {
    int warp = (blockIdx.x * blockDim.x + threadIdx.x) >> 5;
    int lane = threadIdx.x & 31;
    if (warp >= BB * TT * NN) return;
    const float* xr = x + warp * 4;
    float x0 = xr[0], x1 = xr[1], x2 = xr[2], x3 = xr[3];
    int h0 = lane, h1 = lane + 32;
    float w0 = x0 * W[h0] + x1 * W[64 + h0] + x2 * W[128 + h0] + x3 * W[192 + h0];
    float w1 = x0 * W[h1] + x1 * W[64 + h1] + x2 * W[128 + h1] + x3 * W[192 + h1];
    g_Wx[(size_t)warp * 64 + h0] = w0;
    g_Wx[(size_t)warp * 64 + h1] = w1;
    float ps = w0 * att_src[h0] + w1 * att_src[h1];
    float pd = w0 * att_dst[h0] + w1 * att_dst[h1];
#pragma unroll
    for (int o = 16; o; o >>= 1) {
        ps += __shfl_xor_sync(0xFFFFFFFFu, ps, o);
        pd += __shfl_xor_sync(0xFFFFFFFFu, pd, o);
    }
    if (lane == 0) { g_asrc[warp] = ps; g_adst[warp] = pd; }
}

// ---------------- K2: fused GAT softmax + aggregate (two-phase) --------------
// grid (N/128, B*T), 256 threads.
// Phase P: p[j][i] once per pair into smem (MUFU exp), denom partials in regs.
// Phase GEMM: register tile 4i x 8h per thread, packed f32x2 FFMA.
#define TI 128
#define TJ 32

union F4U2 { float4 f4; unsigned long long u2[2]; };

__global__ __launch_bounds__(256) void k_att(const float* __restrict__ adj,
                                             const float* __restrict__ bias) {
    __shared__ __align__(16) float s_wx[TJ][HH];     // 8 KB
    __shared__ __align__(16) float s_p[TJ][TI];      // 16 KB
    __shared__ __align__(16) float s_dpart[8][TI];   // 4 KB
    __shared__ float s_den[TI];

    int bt  = blockIdx.y;
    int i0  = blockIdx.x * TI;
    int tid = threadIdx.x;

    // P-phase mapping: thread covers 4 fixed i columns, 4 j rows per tile
    int pj = tid >> 5;          // 0..7
    int pc = (tid & 31) * 4;    // i column base (0..124)
    const float4 adst4 = *(const float4*)&g_adst[bt * NN + i0 + pc];
    float d0 = 0.f, d1 = 0.f, d2 = 0.f, d3 = 0.f;

    // GEMM mapping: 4 i rows x 8 h cols per thread
    int ig = tid >> 3;          // 0..31 -> i = ig*4 + ii
    int hg = tid & 7;           // 0..7  -> h = hg*8 + k
    unsigned long long acc[16]; // [ii][hpair]
#pragma unroll
    for (int k = 0; k < 16; k++) acc[k] = 0ULL;

    const float* adjbt = adj + (size_t)bt * NN * NN;
    const float* wxbt  = g_Wx + (size_t)bt * NN * HH;
    const float* asbt  = g_asrc + bt * NN;

    for (int j0 = 0; j0 < NN; j0 += TJ) {
        __syncthreads();   // previous GEMM reads done before overwriting tiles

        // load Wx tile: 32 x 64 floats, coalesced float4
#pragma unroll
        for (int u = 0; u < 2; u++) {
            int idx = tid + u * 256;
            int jr  = idx >> 4;
            int cc  = (idx & 15) * 4;
            *(float4*)&s_wx[jr][cc] = *(const float4*)&wxbt[(size_t)(j0 + jr) * HH + cc];
        }

        // P phase: 4 j rows x 4 i cols per thread
#pragma unroll
        for (int u = 0; u < 4; u++) {
            int jr = pj + u * 8;
            int jg = j0 + jr;
            float aj = __ldg(&asbt[jg]);
            float4 a4 = *(const float4*)&adjbt[(size_t)jg * NN + i0 + pc];
            float v0 = adst4.x + aj, v1 = adst4.y + aj, v2 = adst4.z + aj, v3 = adst4.w + aj;
            float e0 = v0 > 0.f ? v0 : 0.2f * v0;
            float e1 = v1 > 0.f ? v1 : 0.2f * v1;
            float e2 = v2 > 0.f ? v2 : 0.2f * v2;
            float e3 = v3 > 0.f ? v3 : 0.2f * v3;
            bool m0 = (a4.x != 0.f) || (jg == i0 + pc + 0);
            bool m1 = (a4.y != 0.f) || (jg == i0 + pc + 1);
            bool m2 = (a4.z != 0.f) || (jg == i0 + pc + 2);
            bool m3 = (a4.w != 0.f) || (jg == i0 + pc + 3);
            float p0 = m0 ? __expf(e0) : 0.f;
            float p1 = m1 ? __expf(e1) : 0.f;
            float p2 = m2 ? __expf(e2) : 0.f;
            float p3 = m3 ? __expf(e3) : 0.f;
            d0 += p0; d1 += p1; d2 += p2; d3 += p3;
            *(float4*)&s_p[jr][pc] = make_float4(p0, p1, p2, p3);
        }
        __syncthreads();

        // GEMM phase: C[4i][8h] += P[4i][j] * Wx[j][8h]
#pragma unroll 8
        for (int j = 0; j < TJ; j++) {
            float4 p4 = *(const float4*)&s_p[j][ig * 4];
            F4U2 wa, wb;
            wa.f4 = *(const float4*)&s_wx[j][hg * 8];
            wb.f4 = *(const float4*)&s_wx[j][hg * 8 + 4];
            unsigned long long pp0, pp1, pp2, pp3;
            asm("mov.b64 %0, {%1, %1};" : "=l"(pp0) : "f"(p4.x));
            asm("mov.b64 %0, {%1, %1};" : "=l"(pp1) : "f"(p4.y));
            asm("mov.b64 %0, {%1, %1};" : "=l"(pp2) : "f"(p4.z));
            asm("mov.b64 %0, {%1, %1};" : "=l"(pp3) : "f"(p4.w));
            asm("fma.rn.f32x2 %0, %1, %2, %0;" : "+l"(acc[0])  : "l"(pp0), "l"(wa.u2[0]));
            asm("fma.rn.f32x2 %0, %1, %2, %0;" : "+l"(acc[1])  : "l"(pp0), "l"(wa.u2[1]));
            asm("fma.rn.f32x2 %0, %1, %2, %0;" : "+l"(acc[2])  : "l"(pp0), "l"(wb.u2[0]));
            asm("fma.rn.f32x2 %0, %1, %2, %0;" : "+l"(acc[3])  : "l"(pp0), "l"(wb.u2[1]));
            asm("fma.rn.f32x2 %0, %1, %2, %0;" : "+l"(acc[4])  : "l"(pp1), "l"(wa.u2[0]));
            asm("fma.rn.f32x2 %0, %1, %2, %0;" : "+l"(acc[5])  : "l"(pp1), "l"(wa.u2[1]));
            asm("fma.rn.f32x2 %0, %1, %2, %0;" : "+l"(acc[6])  : "l"(pp1), "l"(wb.u2[0]));
            asm("fma.rn.f32x2 %0, %1, %2, %0;" : "+l"(acc[7])  : "l"(pp1), "l"(wb.u2[1]));
            asm("fma.rn.f32x2 %0, %1, %2, %0;" : "+l"(acc[8])  : "l"(pp2), "l"(wa.u2[0]));
            asm("fma.rn.f32x2 %0, %1, %2, %0;" : "+l"(acc[9])  : "l"(pp2), "l"(wa.u2[1]));
            asm("fma.rn.f32x2 %0, %1, %2, %0;" : "+l"(acc[10]) : "l"(pp2), "l"(wb.u2[0]));
            asm("fma.rn.f32x2 %0, %1, %2, %0;" : "+l"(acc[11]) : "l"(pp2), "l"(wb.u2[1]));
            asm("fma.rn.f32x2 %0, %1, %2, %0;" : "+l"(acc[12]) : "l"(pp3), "l"(wa.u2[0]));
            asm("fma.rn.f32x2 %0, %1, %2, %0;" : "+l"(acc[13]) : "l"(pp3), "l"(wa.u2[1]));
            asm("fma.rn.f32x2 %0, %1, %2, %0;" : "+l"(acc[14]) : "l"(pp3), "l"(wb.u2[0]));
            asm("fma.rn.f32x2 %0, %1, %2, %0;" : "+l"(acc[15]) : "l"(pp3), "l"(wb.u2[1]));
        }
    }

    // denominator reduction: 8 partials per i column
    *(float4*)&s_dpart[pj][pc] = make_float4(d0, d1, d2, d3);
    __syncthreads();
    if (tid < TI) {
        float s = 0.f;
#pragma unroll
        for (int k = 0; k < 8; k++) s += s_dpart[k][tid];
        s_den[tid] = 1.f / s;
    }
    __syncthreads();

    // epilogue: scale + bias, write 4i x 8h
    float b0 = __ldg(&bias[hg * 8 + 0]), b1 = __ldg(&bias[hg * 8 + 1]);
    float b2 = __ldg(&bias[hg * 8 + 2]), b3 = __ldg(&bias[hg * 8 + 3]);
    float b4 = __ldg(&bias[hg * 8 + 4]), b5 = __ldg(&bias[hg * 8 + 5]);
    float b6 = __ldg(&bias[hg * 8 + 6]), b7 = __ldg(&bias[hg * 8 + 7]);
#pragma unroll
    for (int ii = 0; ii < 4; ii++) {
        float rinv = s_den[ig * 4 + ii];
        float f[8];
#pragma unroll
        for (int k = 0; k < 4; k++) {
            float lo, hi;
            asm("mov.b64 {%0, %1}, %2;" : "=f"(lo), "=f"(hi) : "l"(acc[ii * 4 + k]));
            f[k * 2]     = lo * rinv;
            f[k * 2 + 1] = hi * rinv;
        }
        float* out = g_gat + ((size_t)bt * NN + i0 + ig * 4 + ii) * HH + hg * 8;
        *(float4*)&out[0] = make_float4(f[0] + b0, f[1] + b1, f[2] + b2, f[3] + b3);
        *(float4*)&out[4] = make_float4(f[4] + b4, f[5] + b5, f[6] + b6, f[7] + b7);
    }
}

// ---------------- K3: GRU input gates: seq @ W_ih^T + b_ih -------------------
__global__ void k_gates(const float* __restrict__ Wih, const float* __restrict__ bih) {
    __shared__ float sW[12 * 64];
    __shared__ float sb[12];
    for (int i = threadIdx.x; i < 768; i += blockDim.x) sW[i] = Wih[i];
    if (threadIdx.x < 12) sb[threadIdx.x] = bih[threadIdx.x];
    __syncthreads();
    int r = blockIdx.x * blockDim.x + threadIdx.x;
    if (r >= BB * NN * TT) return;
    const float* in = g_gat + (size_t)r * 64;
    float acc[12];
#pragma unroll
    for (int g = 0; g < 12; g++) acc[g] = sb[g];
#pragma unroll
    for (int h4 = 0; h4 < 16; h4++) {
        float4 v = *(const float4*)&in[h4 * 4];
#pragma unroll
        for (int g = 0; g < 12; g++) {
            const float* w = &sW[g * 64 + h4 * 4];
            acc[g] += v.x * w[0] + v.y * w[1] + v.z * w[2] + v.w * w[3];
        }
    }
    float* o = g_gates + (size_t)r * 12;
#pragma unroll
    for (int g = 0; g < 12; g++) o[g] = acc[g];
}

// ---------------- K4: GRU recurrence (hidden=4, T=8), software-pipelined -----
__global__ void k_gru(const float* __restrict__ Whh, const float* __restrict__ bhh) {
    int q = blockIdx.x * blockDim.x + threadIdx.x;
    if (q >= BB * NN) return;
    float Wl[48];
#pragma unroll
    for (int i = 0; i < 48; i++) Wl[i] = Whh[i];
    float bl[12];
#pragma unroll
    for (int i = 0; i < 12; i++) bl[i] = bhh[i];

    const float* gbase = g_gates + (size_t)q * 8 * 12;
    float4 c0 = *(const float4*)&gbase[0];
    float4 c1 = *(const float4*)&gbase[4];
    float4 c2 = *(const float4*)&gbase[8];

    float h[4] = {0.f, 0.f, 0.f, 0.f};
    for (int s = 0; s < 8; s++) {
        float gxr[12] = {c0.x, c0.y, c0.z, c0.w, c1.x, c1.y, c1.z, c1.w,
                         c2.x, c2.y, c2.z, c2.w};
        if (s < 7) {  // prefetch next step's gates
            c0 = *(const float4*)&gbase[(s + 1) * 12 + 0];
            c1 = *(const float4*)&gbase[(s + 1) * 12 + 4];
            c2 = *(const float4*)&gbase[(s + 1) * 12 + 8];
        }
        float gh[12];
#pragma unroll
        for (int g = 0; g < 12; g++) {
            gh[g] = bl[g] + h[0] * Wl[g * 4 + 0] + h[1] * Wl[g * 4 + 1]
                          + h[2] * Wl[g * 4 + 2] + h[3] * Wl[g * 4 + 3];
        }
        float hn[4];
#pragma unroll
        for (int f = 0; f < 4; f++) {
            float r  = fsigmoid(gxr[f]     + gh[f]);
            float z  = fsigmoid(gxr[4 + f] + gh[4 + f]);
            float nc = ftanh(gxr[8 + f] + r * gh[8 + f]);
            hn[f] = (1.f - z) * nc + z * h[f];
        }
#pragma unroll
        for (int f = 0; f < 4; f++) {
            h[f] = hn[f];
            g_gru[(size_t)(q * 8 + s) * 4 + f] = h[f];
        }
    }
}

// ---------------- K5: Conv2d(T=8 -> 12, 3x3, SAME over (N,4)) + Linear(4->2) -
__global__ void k_conv(const float* __restrict__ cW, const float* __restrict__ cb,
                       const float* __restrict__ oW, const float* __restrict__ ob,
                       float* __restrict__ out) {
    __shared__ float sg[130][33];
    __shared__ float sw[CCO * TT * 9];
    __shared__ float sow[8], sob[2], scb[CCO];

    int b   = blockIdx.y;
    int n0  = blockIdx.x * 128;
    int tid = threadIdx.x;

    for (int i = tid; i < CCO * TT * 9; i += 128) sw[i] = cW[i];
    if (tid < 8)   sow[tid] = oW[tid];
    if (tid < 2)   sob[tid] = ob[tid];
    if (tid < CCO) scb[tid] = cb[tid];

    for (int i = tid; i < 130 * 32; i += 128) {
        int nl = i >> 5;
        int c  = i & 31;
        int n  = n0 + nl - 1;
        float v = 0.f;
        if (n >= 0 && n < NN)
            v = g_gru[(((size_t)b * NN + n) * TT) * FF + c];
        sg[nl][c] = v;
    }
    __syncthreads();

    int nl = tid;
    for (int co = 0; co < CCO; co++) {
        float y0 = scb[co], y1 = scb[co], y2 = scb[co], y3 = scb[co];
#pragma unroll
        for (int ci = 0; ci < TT; ci++) {
#pragma unroll
            for (int kh = 0; kh < 3; kh++) {
                const float* row = &sg[nl + kh][ci * 4];
                float r0 = row[0], r1 = row[1], r2 = row[2], r3 = row[3];
                const float* w = &sw[(co * TT + ci) * 9 + kh * 3];
                float w0 = w[0], w1 = w[1], w2 = w[2];
                y0 += w1 * r0 + w2 * r1;
                y1 += w0 * r0 + w1 * r1 + w2 * r2;
                y2 += w0 * r1 + w1 * r2 + w2 * r3;
                y3 += w0 * r2 + w1 * r3;
            }
        }
        float o0 = sob[0] + y0 * sow[0] + y1 * sow[1] + y2 * sow[2] + y3 * sow[3];
        float o1 = sob[1] + y0 * sow[4] + y1 * sow[5] + y2 * sow[6] + y3 * sow[7];
        size_t oi = (((size_t)b * CCO + co) * NN + (n0 + nl)) * 2;
        out[oi]     = o0;
        out[oi + 1] = o1;
    }
}

// -----------------------------------------------------------------------------
extern "C" void kernel_launch(void* const* d_in, const int* in_sizes, int n_in,
                              void* d_out, int out_size) {
    const float* x        = (const float*)d_in[0];
    const float* adj      = (const float*)d_in[1];
    const float* gat_W    = (const float*)d_in[2];
    const float* att_src  = (const float*)d_in[3];
    const float* att_dst  = (const float*)d_in[4];
    const float* gat_bias = (const float*)d_in[5];
    const float* gru_Wih  = (const float*)d_in[6];
    const float* gru_Whh  = (const float*)d_in[7];
    const float* gru_bih  = (const float*)d_in[8];
    const float* gru_bhh  = (const float*)d_in[9];
    const float* conv_W   = (const float*)d_in[10];
    const float* conv_b   = (const float*)d_in[11];
    const float* out_W    = (const float*)d_in[12];
    const float* out_b    = (const float*)d_in[13];
    float* out = (float*)d_out;

    k_wx<<<(BB * TT * NN) / 8, 256>>>(x, gat_W, att_src, att_dst);

    dim3 g2(NN / TI, BB * TT);
    k_att<<<g2, 256>>>(adj, gat_bias);

    k_gates<<<(BB * NN * TT) / 256, 256>>>(gru_Wih, gru_bih);

    k_gru<<<(BB * NN) / 128, 128>>>(gru_Whh, gru_bhh);

    dim3 g5(NN / 128, BB);
    k_conv<<<g5, 128>>>(conv_W, conv_b, out_W, out_b, out);
}

// round 4
// speedup vs baseline: 1.7898x; 1.2477x over previous
#include <cuda_runtime.h>
#include <cstdint>

#define BB 32
#define TT 8
#define NN 512
#define FF 4
#define HH 64
#define CCO 12

// ---------------- scratch (static device globals; no allocation) -------------
__device__ float g_Wx[BB * TT * NN * HH];      // 8,388,608 floats
__device__ float g_asrc[BB * TT * NN];
__device__ float g_adst[BB * TT * NN];
__device__ float g_gat[BB * TT * NN * HH];
__device__ float g_gates[BB * NN * TT * 12];
__device__ float g_gru[BB * NN * TT * FF];

__device__ __forceinline__ float fsigmoid(float x) { return 1.f / (1.f + __expf(-x)); }
__device__ __forceinline__ float ftanh(float x)    { return tanhf(x); }

// ---------------- K1: Wx = x @ gat_W ; a_src, a_dst --------------------------
__global__ void k_wx(const float* __restrict__ x, const float* __restrict__ W,
                     const float* __restrict__ att_src, const float* __restrict__ att_dst) {
    int warp = (blockIdx.x * blockDim.x + threadIdx.x) >> 5;
    int lane = threadIdx.x & 31;
    if (warp >= BB * TT * NN) return;
    const float* xr = x + warp * 4;
    float x0 = xr[0], x1 = xr[1], x2 = xr[2], x3 = xr[3];
    int h0 = lane, h1 = lane + 32;
    float w0 = x0 * W[h0] + x1 * W[64 + h0] + x2 * W[128 + h0] + x3 * W[192 + h0];
    float w1 = x0 * W[h1] + x1 * W[64 + h1] + x2 * W[128 + h1] + x3 * W[192 + h1];
    g_Wx[(size_t)warp * 64 + h0] = w0;
    g_Wx[(size_t)warp * 64 + h1] = w1;
    float ps = w0 * att_src[h0] + w1 * att_src[h1];
    float pd = w0 * att_dst[h0] + w1 * att_dst[h1];
#pragma unroll
    for (int o = 16; o; o >>= 1) {
        ps += __shfl_xor_sync(0xFFFFFFFFu, ps, o);
        pd += __shfl_xor_sync(0xFFFFFFFFu, pd, o);
    }
    if (lane == 0) { g_asrc[warp] = ps; g_adst[warp] = pd; }
}

// ---------------- K2: fused GAT softmax + aggregate --------------------------
// Software-pipelined: register-prefetch gmem for tile t+1 during tile t's GEMM,
// double-buffered smem, ONE barrier per tile.
#define TI 128
#define TJ 32
#define NTILE (NN / TJ)

union F4U2 { float4 f4; unsigned long long u2[2]; };

__global__ __launch_bounds__(256, 2) void k_att(const float* __restrict__ adj,
                                                const float* __restrict__ bias) {
    __shared__ __align__(16) float s_wx[2][TJ][HH];   // 16 KB
    __shared__ __align__(16) float s_p[2][TJ][TI];    // 32 KB
    __shared__ __align__(16) float s_dpart[8][TI];    // 4 KB
    __shared__ float s_den[TI];

    int bt  = blockIdx.y;
    int i0  = blockIdx.x * TI;
    int tid = threadIdx.x;

    // P-phase mapping: 4 i columns x 4 j rows per thread
    int pj = tid >> 5;          // 0..7
    int pc = (tid & 31) * 4;    // i column base
    const float4 adst4 = *(const float4*)&g_adst[bt * NN + i0 + pc];
    float d0 = 0.f, d1 = 0.f, d2 = 0.f, d3 = 0.f;

    // GEMM mapping: 4 i rows x 8 h cols per thread
    int ig = tid >> 3;
    int hg = tid & 7;
    unsigned long long acc[16];
#pragma unroll
    for (int k = 0; k < 16; k++) acc[k] = 0ULL;

    const float* adjbt = adj + (size_t)bt * NN * NN;
    const float* wxbt  = g_Wx + (size_t)bt * NN * HH;
    const float* asbt  = g_asrc + bt * NN;

    // prefetch registers
    float4 pwx0, pwx1;
    float4 padj[4];
    float  pas[4];

    {   // prefetch tile 0
        int jr0 = tid >> 4,          cc0 = (tid & 15) * 4;
        int jr1 = (tid + 256) >> 4,  cc1 = (tid & 15) * 4;
        pwx0 = *(const float4*)&wxbt[(size_t)jr0 * HH + cc0];
        pwx1 = *(const float4*)&wxbt[(size_t)jr1 * HH + cc1];
#pragma unroll
        for (int u = 0; u < 4; u++) {
            int jg = pj + u * 8;
            padj[u] = *(const float4*)&adjbt[(size_t)jg * NN + i0 + pc];
            pas[u]  = __ldg(&asbt[jg]);
        }
    }

    for (int t = 0; t < NTILE; t++) {
        int buf = t & 1;
        int j0  = t * TJ;

        // stage Wx tile from prefetch regs
        {
            int jr0 = tid >> 4,         cc0 = (tid & 15) * 4;
            int jr1 = (tid + 256) >> 4, cc1 = (tid & 15) * 4;
            *(float4*)&s_wx[buf][jr0][cc0] = pwx0;
            *(float4*)&s_wx[buf][jr1][cc1] = pwx1;
        }
        // P phase from prefetch regs
#pragma unroll
        for (int u = 0; u < 4; u++) {
            int jr = pj + u * 8;
            int jg = j0 + jr;
            float aj = pas[u];
            float4 a4 = padj[u];
            float v0 = adst4.x + aj, v1 = adst4.y + aj, v2 = adst4.z + aj, v3 = adst4.w + aj;
            float e0 = v0 > 0.f ? v0 : 0.2f * v0;
            float e1 = v1 > 0.f ? v1 : 0.2f * v1;
            float e2 = v2 > 0.f ? v2 : 0.2f * v2;
            float e3 = v3 > 0.f ? v3 : 0.2f * v3;
            bool m0 = (a4.x != 0.f) || (jg == i0 + pc + 0);
            bool m1 = (a4.y != 0.f) || (jg == i0 + pc + 1);
            bool m2 = (a4.z != 0.f) || (jg == i0 + pc + 2);
            bool m3 = (a4.w != 0.f) || (jg == i0 + pc + 3);
            float p0 = m0 ? __expf(e0) : 0.f;
            float p1 = m1 ? __expf(e1) : 0.f;
            float p2 = m2 ? __expf(e2) : 0.f;
            float p3 = m3 ? __expf(e3) : 0.f;
            d0 += p0; d1 += p1; d2 += p2; d3 += p3;
            *(float4*)&s_p[buf][jr][pc] = make_float4(p0, p1, p2, p3);
        }
        // issue prefetch for tile t+1 (overlaps with GEMM below)
        if (t < NTILE - 1) {
            int jn = j0 + TJ;
            int jr0 = tid >> 4,         cc0 = (tid & 15) * 4;
            int jr1 = (tid + 256) >> 4, cc1 = (tid & 15) * 4;
            pwx0 = *(const float4*)&wxbt[(size_t)(jn + jr0) * HH + cc0];
            pwx1 = *(const float4*)&wxbt[(size_t)(jn + jr1) * HH + cc1];
#pragma unroll
            for (int u = 0; u < 4; u++) {
                int jg = jn + pj + u * 8;
                padj[u] = *(const float4*)&adjbt[(size_t)jg * NN + i0 + pc];
                pas[u]  = __ldg(&asbt[jg]);
            }
        }
        __syncthreads();

        // GEMM: C[4i][8h] += P[4i][j] * Wx[j][8h]
#pragma unroll 8
        for (int j = 0; j < TJ; j++) {
            float4 p4 = *(const float4*)&s_p[buf][j][ig * 4];
            F4U2 wa, wb;
            wa.f4 = *(const float4*)&s_wx[buf][j][hg * 8];
            wb.f4 = *(const float4*)&s_wx[buf][j][hg * 8 + 4];
            unsigned long long pp0, pp1, pp2, pp3;
            asm("mov.b64 %0, {%1, %1};" : "=l"(pp0) : "f"(p4.x));
            asm("mov.b64 %0, {%1, %1};" : "=l"(pp1) : "f"(p4.y));
            asm("mov.b64 %0, {%1, %1};" : "=l"(pp2) : "f"(p4.z));
            asm("mov.b64 %0, {%1, %1};" : "=l"(pp3) : "f"(p4.w));
            asm("fma.rn.f32x2 %0, %1, %2, %0;" : "+l"(acc[0])  : "l"(pp0), "l"(wa.u2[0]));
            asm("fma.rn.f32x2 %0, %1, %2, %0;" : "+l"(acc[1])  : "l"(pp0), "l"(wa.u2[1]));
            asm("fma.rn.f32x2 %0, %1, %2, %0;" : "+l"(acc[2])  : "l"(pp0), "l"(wb.u2[0]));
            asm("fma.rn.f32x2 %0, %1, %2, %0;" : "+l"(acc[3])  : "l"(pp0), "l"(wb.u2[1]));
            asm("fma.rn.f32x2 %0, %1, %2, %0;" : "+l"(acc[4])  : "l"(pp1), "l"(wa.u2[0]));
            asm("fma.rn.f32x2 %0, %1, %2, %0;" : "+l"(acc[5])  : "l"(pp1), "l"(wa.u2[1]));
            asm("fma.rn.f32x2 %0, %1, %2, %0;" : "+l"(acc[6])  : "l"(pp1), "l"(wb.u2[0]));
            asm("fma.rn.f32x2 %0, %1, %2, %0;" : "+l"(acc[7])  : "l"(pp1), "l"(wb.u2[1]));
            asm("fma.rn.f32x2 %0, %1, %2, %0;" : "+l"(acc[8])  : "l"(pp2), "l"(wa.u2[0]));
            asm("fma.rn.f32x2 %0, %1, %2, %0;" : "+l"(acc[9])  : "l"(pp2), "l"(wa.u2[1]));
            asm("fma.rn.f32x2 %0, %1, %2, %0;" : "+l"(acc[10]) : "l"(pp2), "l"(wb.u2[0]));
            asm("fma.rn.f32x2 %0, %1, %2, %0;" : "+l"(acc[11]) : "l"(pp2), "l"(wb.u2[1]));
            asm("fma.rn.f32x2 %0, %1, %2, %0;" : "+l"(acc[12]) : "l"(pp3), "l"(wa.u2[0]));
            asm("fma.rn.f32x2 %0, %1, %2, %0;" : "+l"(acc[13]) : "l"(pp3), "l"(wa.u2[1]));
            asm("fma.rn.f32x2 %0, %1, %2, %0;" : "+l"(acc[14]) : "l"(pp3), "l"(wb.u2[0]));
            asm("fma.rn.f32x2 %0, %1, %2, %0;" : "+l"(acc[15]) : "l"(pp3), "l"(wb.u2[1]));
        }
    }

    // denominator reduction
    __syncthreads();
    *(float4*)&s_dpart[pj][pc] = make_float4(d0, d1, d2, d3);
    __syncthreads();
    if (tid < TI) {
        float s = 0.f;
#pragma unroll
        for (int k = 0; k < 8; k++) s += s_dpart[k][tid];
        s_den[tid] = 1.f / s;
    }
    __syncthreads();

    // epilogue
    float b0 = __ldg(&bias[hg * 8 + 0]), b1 = __ldg(&bias[hg * 8 + 1]);
    float b2 = __ldg(&bias[hg * 8 + 2]), b3 = __ldg(&bias[hg * 8 + 3]);
    float b4 = __ldg(&bias[hg * 8 + 4]), b5 = __ldg(&bias[hg * 8 + 5]);
    float b6 = __ldg(&bias[hg * 8 + 6]), b7 = __ldg(&bias[hg * 8 + 7]);
#pragma unroll
    for (int ii = 0; ii < 4; ii++) {
        float rinv = s_den[ig * 4 + ii];
        float f[8];
#pragma unroll
        for (int k = 0; k < 4; k++) {
            float lo, hi;
            asm("mov.b64 {%0, %1}, %2;" : "=f"(lo), "=f"(hi) : "l"(acc[ii * 4 + k]));
            f[k * 2]     = lo * rinv;
            f[k * 2 + 1] = hi * rinv;
        }
        float* out = g_gat + ((size_t)bt * NN + i0 + ig * 4 + ii) * HH + hg * 8;
        *(float4*)&out[0] = make_float4(f[0] + b0, f[1] + b1, f[2] + b2, f[3] + b3);
        *(float4*)&out[4] = make_float4(f[4] + b4, f[5] + b5, f[6] + b6, f[7] + b7);
    }
}

// ---------------- K3: GRU input gates ----------------------------------------
__global__ void k_gates(const float* __restrict__ Wih, const float* __restrict__ bih) {
    __shared__ float sW[12 * 64];
    __shared__ float sb[12];
    for (int i = threadIdx.x; i < 768; i += blockDim.x) sW[i] = Wih[i];
    if (threadIdx.x < 12) sb[threadIdx.x] = bih[threadIdx.x];
    __syncthreads();
    int r = blockIdx.x * blockDim.x + threadIdx.x;
    if (r >= BB * NN * TT) return;
    const float* in = g_gat + (size_t)r * 64;
    float acc[12];
#pragma unroll
    for (int g = 0; g < 12; g++) acc[g] = sb[g];
#pragma unroll
    for (int h4 = 0; h4 < 16; h4++) {
        float4 v = *(const float4*)&in[h4 * 4];
#pragma unroll
        for (int g = 0; g < 12; g++) {
            const float* w = &sW[g * 64 + h4 * 4];
            acc[g] += v.x * w[0] + v.y * w[1] + v.z * w[2] + v.w * w[3];
        }
    }
    float* o = g_gates + (size_t)r * 12;
#pragma unroll
    for (int g = 0; g < 12; g++) o[g] = acc[g];
}

// ---------------- K4: GRU recurrence -----------------------------------------
__global__ void k_gru(const float* __restrict__ Whh, const float* __restrict__ bhh) {
    int q = blockIdx.x * blockDim.x + threadIdx.x;
    if (q >= BB * NN) return;
    float Wl[48];
#pragma unroll
    for (int i = 0; i < 48; i++) Wl[i] = Whh[i];
    float bl[12];
#pragma unroll
    for (int i = 0; i < 12; i++) bl[i] = bhh[i];

    const float* gbase = g_gates + (size_t)q * 8 * 12;
    float4 c0 = *(const float4*)&gbase[0];
    float4 c1 = *(const float4*)&gbase[4];
    float4 c2 = *(const float4*)&gbase[8];

    float h[4] = {0.f, 0.f, 0.f, 0.f};
    for (int s = 0; s < 8; s++) {
        float gxr[12] = {c0.x, c0.y, c0.z, c0.w, c1.x, c1.y, c1.z, c1.w,
                         c2.x, c2.y, c2.z, c2.w};
        if (s < 7) {
            c0 = *(const float4*)&gbase[(s + 1) * 12 + 0];
            c1 = *(const float4*)&gbase[(s + 1) * 12 + 4];
            c2 = *(const float4*)&gbase[(s + 1) * 12 + 8];
        }
        float gh[12];
#pragma unroll
        for (int g = 0; g < 12; g++) {
            gh[g] = bl[g] + h[0] * Wl[g * 4 + 0] + h[1] * Wl[g * 4 + 1]
                          + h[2] * Wl[g * 4 + 2] + h[3] * Wl[g * 4 + 3];
        }
        float hn[4];
#pragma unroll
        for (int f = 0; f < 4; f++) {
            float r  = fsigmoid(gxr[f]     + gh[f]);
            float z  = fsigmoid(gxr[4 + f] + gh[4 + f]);
            float nc = ftanh(gxr[8 + f] + r * gh[8 + f]);
            hn[f] = (1.f - z) * nc + z * h[f];
        }
#pragma unroll
        for (int f = 0; f < 4; f++) {
            h[f] = hn[f];
            g_gru[(size_t)(q * 8 + s) * 4 + f] = h[f];
        }
    }
}

// ---------------- K5: Conv2d + Linear ----------------------------------------
__global__ void k_conv(const float* __restrict__ cW, const float* __restrict__ cb,
                       const float* __restrict__ oW, const float* __restrict__ ob,
                       float* __restrict__ out) {
    __shared__ float sg[130][33];
    __shared__ float sw[CCO * TT * 9];
    __shared__ float sow[8], sob[2], scb[CCO];

    int b   = blockIdx.y;
    int n0  = blockIdx.x * 128;
    int tid = threadIdx.x;

    for (int i = tid; i < CCO * TT * 9; i += 128) sw[i] = cW[i];
    if (tid < 8)   sow[tid] = oW[tid];
    if (tid < 2)   sob[tid] = ob[tid];
    if (tid < CCO) scb[tid] = cb[tid];

    for (int i = tid; i < 130 * 32; i += 128) {
        int nl = i >> 5;
        int c  = i & 31;
        int n  = n0 + nl - 1;
        float v = 0.f;
        if (n >= 0 && n < NN)
            v = g_gru[(((size_t)b * NN + n) * TT) * FF + c];
        sg[nl][c] = v;
    }
    __syncthreads();

    int nl = tid;
    for (int co = 0; co < CCO; co++) {
        float y0 = scb[co], y1 = scb[co], y2 = scb[co], y3 = scb[co];
#pragma unroll
        for (int ci = 0; ci < TT; ci++) {
#pragma unroll
            for (int kh = 0; kh < 3; kh++) {
                const float* row = &sg[nl + kh][ci * 4];
                float r0 = row[0], r1 = row[1], r2 = row[2], r3 = row[3];
                const float* w = &sw[(co * TT + ci) * 9 + kh * 3];
                float w0 = w[0], w1 = w[1], w2 = w[2];
                y0 += w1 * r0 + w2 * r1;
                y1 += w0 * r0 + w1 * r1 + w2 * r2;
                y2 += w0 * r1 + w1 * r2 + w2 * r3;
                y3 += w0 * r2 + w1 * r3;
            }
        }
        float o0 = sob[0] + y0 * sow[0] + y1 * sow[1] + y2 * sow[2] + y3 * sow[3];
        float o1 = sob[1] + y0 * sow[4] + y1 * sow[5] + y2 * sow[6] + y3 * sow[7];
        size_t oi = (((size_t)b * CCO + co) * NN + (n0 + nl)) * 2;
        out[oi]     = o0;
        out[oi + 1] = o1;
    }
}

// -----------------------------------------------------------------------------
extern "C" void kernel_launch(void* const* d_in, const int* in_sizes, int n_in,
                              void* d_out, int out_size) {
    const float* x        = (const float*)d_in[0];
    const float* adj      = (const float*)d_in[1];
    const float* gat_W    = (const float*)d_in[2];
    const float* att_src  = (const float*)d_in[3];
    const float* att_dst  = (const float*)d_in[4];
    const float* gat_bias = (const float*)d_in[5];
    const float* gru_Wih  = (const float*)d_in[6];
    const float* gru_Whh  = (const float*)d_in[7];
    const float* gru_bih  = (const float*)d_in[8];
    const float* gru_bhh  = (const float*)d_in[9];
    const float* conv_W   = (const float*)d_in[10];
    const float* conv_b   = (const float*)d_in[11];
    const float* out_W    = (const float*)d_in[12];
    const float* out_b    = (const float*)d_in[13];
    float* out = (float*)d_out;

    k_wx<<<(BB * TT * NN) / 8, 256>>>(x, gat_W, att_src, att_dst);

    dim3 g2(NN / TI, BB * TT);
    k_att<<<g2, 256>>>(adj, gat_bias);

    k_gates<<<(BB * NN * TT) / 256, 256>>>(gru_Wih, gru_bih);

    k_gru<<<(BB * NN) / 128, 128>>>(gru_Whh, gru_bhh);

    dim3 g5(NN / 128, BB);
    k_conv<<<g5, 128>>>(conv_W, conv_b, out_W, out_b, out);
}

// round 5
// speedup vs baseline: 6.3537x; 3.5499x over previous
#include <cuda_runtime.h>
#include <cstdint>

#define BB 32
#define TT 8
#define NN 512
#define FF 4
#define HH 64
#define CCO 12

// ---------------- scratch ----------------------------------------------------
__device__ float g_asrc[BB * TT * NN];
__device__ float g_adst[BB * TT * NN];
__device__ float g_y[BB * TT * NN * FF];       // normalized aggregate, 2 MB
__device__ float g_gru[BB * NN * TT * FF];
__device__ float g_M[12 * FF];                 // W_ih @ W^T
__device__ float g_c[12];                      // W_ih @ bias + b_ih

__device__ __forceinline__ float fsigmoid(float x) { return 1.f / (1.f + __expf(-x)); }
__device__ __forceinline__ float ftanh(float x)    { return tanhf(x); }

// ---------------- K0: precompute a_src, a_dst (rank-4 trick) -----------------
// ws[f] = sum_h W[f,h]*att_src[h]; asrc[r] = x[r,:].ws   (same for dst)
__global__ void k_pre(const float* __restrict__ x, const float* __restrict__ W,
                      const float* __restrict__ att_src, const float* __restrict__ att_dst) {
    __shared__ float s_ws[4], s_wd[4];
    int tid = threadIdx.x;
    if (tid < 256) {
        const float* av = (tid < 128) ? att_src : att_dst;
        int t2   = tid & 127;
        int f    = t2 >> 5;
        int lane = t2 & 31;
        float p = W[f * 64 + lane] * av[lane] + W[f * 64 + lane + 32] * av[lane + 32];
#pragma unroll
        for (int o = 16; o; o >>= 1) p += __shfl_xor_sync(0xFFFFFFFFu, p, o);
        if (lane == 0) { if (tid < 128) s_ws[f] = p; else s_wd[f] = p; }
    }
    __syncthreads();
    int r = blockIdx.x * blockDim.x + tid;
    if (r >= BB * TT * NN) return;
    float4 xv = *(const float4*)&x[r * 4];
    g_asrc[r] = xv.x * s_ws[0] + xv.y * s_ws[1] + xv.z * s_ws[2] + xv.w * s_ws[3];
    g_adst[r] = xv.x * s_wd[0] + xv.y * s_wd[1] + xv.z * s_wd[2] + xv.w * s_wd[3];
}

// ---------------- K0b: fold GAT projection into GRU input matrix -------------
// M[g,f] = sum_h Wih[g,h]*W[f,h];  c[g] = sum_h Wih[g,h]*bias[h] + bih[g]
__global__ void k_mat(const float* __restrict__ Wih, const float* __restrict__ W,
                      const float* __restrict__ bias, const float* __restrict__ bih) {
    int t = threadIdx.x;
    if (t < 48) {
        int g = t >> 2, f = t & 3;
        float s = 0.f;
        for (int h = 0; h < 64; h++) s += Wih[g * 64 + h] * W[f * 64 + h];
        g_M[g * 4 + f] = s;
    } else if (t < 60) {
        int g = t - 48;
        float s = bih[g];
        for (int h = 0; h < 64; h++) s += Wih[g * 64 + h] * bias[h];
        g_c[g] = s;
    }
}

// ---------------- K2: fused GAT softmax + F-space aggregate ------------------
// grid (N/128, B*T), 256 threads. P-phase -> smem p tile; accumulate y[i][4].
#define TI 128
#define TJ 32
#define NTILE (NN / TJ)

__global__ __launch_bounds__(256) void k_att(const float* __restrict__ adj,
                                             const float* __restrict__ x) {
    __shared__ __align__(16) float4 s_x[NN];        // 8 KB
    __shared__ float s_asrc[NN];                    // 2 KB
    __shared__ __align__(16) float s_p[2][TJ][TI];  // 32 KB

    int bt  = blockIdx.y;
    int i0  = blockIdx.x * TI;
    int tid = threadIdx.x;

    const float*  adjbt = adj + (size_t)bt * NN * NN;
    const float4* xbt   = (const float4*)(x + (size_t)bt * NN * 4);

    // load x + asrc tiles once
    for (int idx = tid; idx < NN; idx += 256) {
        s_x[idx]    = xbt[idx];
        s_asrc[idx] = g_asrc[bt * NN + idx];
    }

    // P-phase mapping: 4 j rows x 4 i cols per thread
    int pj = tid >> 5;
    int pc = (tid & 31) * 4;
    const float4 adst4 = *(const float4*)&g_adst[bt * NN + i0 + pc];

    // accumulate mapping: 2 threads per i row, 2 f each
    int il = tid >> 1;
    int fp = (tid & 1) * 2;
    float a0 = 0.f, a1 = 0.f, den = 0.f;

    // prefetch adj tile 0
    float4 padj[4];
#pragma unroll
    for (int u = 0; u < 4; u++)
        padj[u] = *(const float4*)&adjbt[(size_t)(pj + u * 8) * NN + i0 + pc];

    __syncthreads();

    for (int t = 0; t < NTILE; t++) {
        int buf = t & 1;
        int j0  = t * TJ;

        // P phase
#pragma unroll
        for (int u = 0; u < 4; u++) {
            int jr = pj + u * 8;
            int jg = j0 + jr;
            float aj = s_asrc[jg];
            float4 a4 = padj[u];
            float v0 = adst4.x + aj, v1 = adst4.y + aj, v2 = adst4.z + aj, v3 = adst4.w + aj;
            float e0 = v0 > 0.f ? v0 : 0.2f * v0;
            float e1 = v1 > 0.f ? v1 : 0.2f * v1;
            float e2 = v2 > 0.f ? v2 : 0.2f * v2;
            float e3 = v3 > 0.f ? v3 : 0.2f * v3;
            bool m0 = (a4.x != 0.f) || (jg == i0 + pc + 0);
            bool m1 = (a4.y != 0.f) || (jg == i0 + pc + 1);
            bool m2 = (a4.z != 0.f) || (jg == i0 + pc + 2);
            bool m3 = (a4.w != 0.f) || (jg == i0 + pc + 3);
            float p0 = m0 ? __expf(e0) : 0.f;
            float p1 = m1 ? __expf(e1) : 0.f;
            float p2 = m2 ? __expf(e2) : 0.f;
            float p3 = m3 ? __expf(e3) : 0.f;
            *(float4*)&s_p[buf][jr][pc] = make_float4(p0, p1, p2, p3);
        }
        // prefetch next adj tile (overlaps with accumulate below)
        if (t < NTILE - 1) {
            int jn = j0 + TJ;
#pragma unroll
            for (int u = 0; u < 4; u++)
                padj[u] = *(const float4*)&adjbt[(size_t)(jn + pj + u * 8) * NN + i0 + pc];
        }
        __syncthreads();

        // accumulate: y[il][fp..fp+1] += p[j][il] * x[j][fp..fp+1]; den += p
#pragma unroll 8
        for (int j = 0; j < TJ; j++) {
            float p = s_p[buf][j][il];
            float2 xv = *(const float2*)(((const float*)&s_x[j0 + j]) + fp);
            a0 += p * xv.x;
            a1 += p * xv.y;
            den += p;
        }
    }

    float rinv = 1.f / den;
    *(float2*)&g_y[((size_t)bt * NN + i0 + il) * 4 + fp] = make_float2(a0 * rinv, a1 * rinv);
}

// ---------------- K4: GRU with fused input projection ------------------------
// gates_x[g] = c[g] + y.M^T ; recurrence hidden=4, T=8
__global__ void k_gru(const float* __restrict__ Whh, const float* __restrict__ bhh) {
    __shared__ float sM[48], sW[48], sc[12], sb[12];
    int tid = threadIdx.x;
    if (tid < 48)                 sM[tid]       = g_M[tid];
    else if (tid < 96)            sW[tid - 48]  = Whh[tid - 48];
    else if (tid < 108)           sc[tid - 96]  = g_c[tid - 96];
    else if (tid < 120)           sb[tid - 108] = bhh[tid - 108];
    __syncthreads();

    int q = blockIdx.x * blockDim.x + tid;
    if (q >= BB * NN) return;

    // prefetch all 8 timesteps of y (raw .view: rows q*8+s)
    float4 y[8];
#pragma unroll
    for (int s = 0; s < 8; s++)
        y[s] = *(const float4*)&g_y[(size_t)(q * 8 + s) * 4];

    float h[4] = {0.f, 0.f, 0.f, 0.f};
#pragma unroll
    for (int s = 0; s < 8; s++) {
        float gx[12], gh[12];
#pragma unroll
        for (int g = 0; g < 12; g++) {
            gx[g] = sc[g] + y[s].x * sM[g * 4 + 0] + y[s].y * sM[g * 4 + 1]
                          + y[s].z * sM[g * 4 + 2] + y[s].w * sM[g * 4 + 3];
            gh[g] = sb[g] + h[0] * sW[g * 4 + 0] + h[1] * sW[g * 4 + 1]
                          + h[2] * sW[g * 4 + 2] + h[3] * sW[g * 4 + 3];
        }
#pragma unroll
        for (int f = 0; f < 4; f++) {
            float r  = fsigmoid(gx[f]     + gh[f]);
            float z  = fsigmoid(gx[4 + f] + gh[4 + f]);
            float nc = ftanh(gx[8 + f] + r * gh[8 + f]);
            h[f] = (1.f - z) * nc + z * h[f];
        }
#pragma unroll
        for (int f = 0; f < 4; f++)
            g_gru[(size_t)(q * 8 + s) * 4 + f] = h[f];
    }
}

// ---------------- K5: Conv2d(8->12, 3x3, SAME over (N,4)) + Linear(4->2) -----
__global__ void k_conv(const float* __restrict__ cW, const float* __restrict__ cb,
                       const float* __restrict__ oW, const float* __restrict__ ob,
                       float* __restrict__ out) {
    __shared__ float sg[130][33];
    __shared__ float sw[CCO * TT * 9];
    __shared__ float sow[8], sob[2], scb[CCO];

    int b   = blockIdx.y;
    int n0  = blockIdx.x * 128;
    int tid = threadIdx.x;

    for (int i = tid; i < CCO * TT * 9; i += 128) sw[i] = cW[i];
    if (tid < 8)   sow[tid] = oW[tid];
    if (tid < 2)   sob[tid] = ob[tid];
    if (tid < CCO) scb[tid] = cb[tid];

    for (int i = tid; i < 130 * 32; i += 128) {
        int nl = i >> 5;
        int c  = i & 31;
        int n  = n0 + nl - 1;
        float v = 0.f;
        if (n >= 0 && n < NN)
            v = g_gru[(((size_t)b * NN + n) * TT) * FF + c];
        sg[nl][c] = v;
    }
    __syncthreads();

    int nl = tid;
    for (int co = 0; co < CCO; co++) {
        float y0 = scb[co], y1 = scb[co], y2 = scb[co], y3 = scb[co];
#pragma unroll
        for (int ci = 0; ci < TT; ci++) {
#pragma unroll
            for (int kh = 0; kh < 3; kh++) {
                const float* row = &sg[nl + kh][ci * 4];
                float r0 = row[0], r1 = row[1], r2 = row[2], r3 = row[3];
                const float* w = &sw[(co * TT + ci) * 9 + kh * 3];
                float w0 = w[0], w1 = w[1], w2 = w[2];
                y0 += w1 * r0 + w2 * r1;
                y1 += w0 * r0 + w1 * r1 + w2 * r2;
                y2 += w0 * r1 + w1 * r2 + w2 * r3;
                y3 += w0 * r2 + w1 * r3;
            }
        }
        float o0 = sob[0] + y0 * sow[0] + y1 * sow[1] + y2 * sow[2] + y3 * sow[3];
        float o1 = sob[1] + y0 * sow[4] + y1 * sow[5] + y2 * sow[6] + y3 * sow[7];
        size_t oi = (((size_t)b * CCO + co) * NN + (n0 + nl)) * 2;
        out[oi]     = o0;
        out[oi + 1] = o1;
    }
}

// -----------------------------------------------------------------------------
extern "C" void kernel_launch(void* const* d_in, const int* in_sizes, int n_in,
                              void* d_out, int out_size) {
    const float* x        = (const float*)d_in[0];
    const float* adj      = (const float*)d_in[1];
    const float* gat_W    = (const float*)d_in[2];
    const float* att_src  = (const float*)d_in[3];
    const float* att_dst  = (const float*)d_in[4];
    const float* gat_bias = (const float*)d_in[5];
    const float* gru_Wih  = (const float*)d_in[6];
    const float* gru_Whh  = (const float*)d_in[7];
    const float* gru_bih  = (const float*)d_in[8];
    const float* gru_bhh  = (const float*)d_in[9];
    const float* conv_W   = (const float*)d_in[10];
    const float* conv_b   = (const float*)d_in[11];
    const float* out_W    = (const float*)d_in[12];
    const float* out_b    = (const float*)d_in[13];
    float* out = (float*)d_out;

    k_pre<<<(BB * TT * NN) / 256, 256>>>(x, gat_W, att_src, att_dst);
    k_mat<<<1, 64>>>(gru_Wih, gat_W, gat_bias, gru_bih);

    dim3 g2(NN / TI, BB * TT);
    k_att<<<g2, 256>>>(adj, x);

    k_gru<<<(BB * NN) / 128, 128>>>(gru_Whh, gru_bhh);

    dim3 g5(NN / 128, BB);
    k_conv<<<g5, 128>>>(conv_W, conv_b, out_W, out_b, out);
}

// round 6
// speedup vs baseline: 8.4003x; 1.3221x over previous
#include <cuda_runtime.h>
#include <cstdint>

#define BB 32
#define TT 8
#define NN 512
#define FF 4
#define HH 64
#define CCO 12

// ---------------- scratch ----------------------------------------------------
__device__ float g_asrc[BB * TT * NN];
__device__ float g_adst[BB * TT * NN];
__device__ float g_y[BB * TT * NN * FF];       // normalized aggregate, 2 MB
__device__ float g_gru[BB * NN * TT * FF];
__device__ float g_M[12 * FF];                 // W_ih @ W^T
__device__ float g_c[12];                      // W_ih @ bias + b_ih

__device__ __forceinline__ float fsigmoid(float x) { return 1.f / (1.f + __expf(-x)); }
__device__ __forceinline__ float ftanh(float x)    { return tanhf(x); }

// ---------------- K0: precompute a_src, a_dst (rank-4 trick) -----------------
__global__ void k_pre(const float* __restrict__ x, const float* __restrict__ W,
                      const float* __restrict__ att_src, const float* __restrict__ att_dst) {
    __shared__ float s_ws[4], s_wd[4];
    int tid = threadIdx.x;
    if (tid < 256) {
        const float* av = (tid < 128) ? att_src : att_dst;
        int t2   = tid & 127;
        int f    = t2 >> 5;
        int lane = t2 & 31;
        float p = W[f * 64 + lane] * av[lane] + W[f * 64 + lane + 32] * av[lane + 32];
#pragma unroll
        for (int o = 16; o; o >>= 1) p += __shfl_xor_sync(0xFFFFFFFFu, p, o);
        if (lane == 0) { if (tid < 128) s_ws[f] = p; else s_wd[f] = p; }
    }
    __syncthreads();
    int r = blockIdx.x * blockDim.x + tid;
    if (r >= BB * TT * NN) return;
    float4 xv = *(const float4*)&x[r * 4];
    g_asrc[r] = xv.x * s_ws[0] + xv.y * s_ws[1] + xv.z * s_ws[2] + xv.w * s_ws[3];
    g_adst[r] = xv.x * s_wd[0] + xv.y * s_wd[1] + xv.z * s_wd[2] + xv.w * s_wd[3];
}

// ---------------- K0b: fold GAT projection into GRU input matrix -------------
__global__ void k_mat(const float* __restrict__ Wih, const float* __restrict__ W,
                      const float* __restrict__ bias, const float* __restrict__ bih) {
    int t = threadIdx.x;
    if (t < 48) {
        int g = t >> 2, f = t & 3;
        float s = 0.f;
        for (int h = 0; h < 64; h++) s += Wih[g * 64 + h] * W[f * 64 + h];
        g_M[g * 4 + f] = s;
    } else if (t < 60) {
        int g = t - 48;
        float s = bih[g];
        for (int h = 0; h < 64; h++) s += Wih[g * 64 + h] * bias[h];
        g_c[g] = s;
    }
}

// ---------------- K2: fused GAT softmax + F-space aggregate ------------------
// grid (N/128, B*T), 256 threads. Each thread owns 4 i-columns, walks its 4
// j-rows per tile, accumulating y[4i][4f] + den[4i] directly in registers.
// NO barriers in the main loop; one 8-way cross-warp reduction at the end.
#define TI 128
#define TJ 32
#define NTILE (NN / TJ)

__global__ __launch_bounds__(256) void k_att(const float* __restrict__ adj,
                                             const float* __restrict__ x) {
    __shared__ __align__(16) float4 s_x[NN];        // 8 KB
    __shared__ float s_asrc[NN];                    // 2 KB
    __shared__ float s_red[8][TI][5];               // 20 KB  [pj][i][f0..3,den]

    int bt  = blockIdx.y;
    int i0  = blockIdx.x * TI;
    int tid = threadIdx.x;
    int pj  = tid >> 5;          // 0..7 : j sub-row
    int pc  = (tid & 31) * 4;    // i column base

    const float*  adjbt = adj + (size_t)bt * NN * NN;
    const float4* xbt   = (const float4*)(x + (size_t)bt * NN * 4);

    for (int idx = tid; idx < NN; idx += 256) {
        s_x[idx]    = xbt[idx];
        s_asrc[idx] = g_asrc[bt * NN + idx];
    }
    const float4 adst4 = *(const float4*)&g_adst[bt * NN + i0 + pc];

    // prefetch adj tile 0 (rows pj, pj+8, pj+16, pj+24)
    float4 padj[4];
#pragma unroll
    for (int u = 0; u < 4; u++)
        padj[u] = *(const float4*)&adjbt[(size_t)(pj + u * 8) * NN + i0 + pc];

    __syncthreads();

    float4 accv[4] = {{0,0,0,0},{0,0,0,0},{0,0,0,0},{0,0,0,0}};  // [ii].{f}
    float  den[4]  = {0.f, 0.f, 0.f, 0.f};

    for (int t = 0; t < NTILE; t++) {
        int j0 = t * TJ;
        float4 cur[4];
#pragma unroll
        for (int u = 0; u < 4; u++) cur[u] = padj[u];
        if (t < NTILE - 1) {
#pragma unroll
            for (int u = 0; u < 4; u++)
                padj[u] = *(const float4*)&adjbt[(size_t)(j0 + TJ + pj + u * 8) * NN + i0 + pc];
        }
#pragma unroll
        for (int u = 0; u < 4; u++) {
            int jg = j0 + pj + u * 8;
            float  aj = s_asrc[jg];          // broadcast within warp
            float4 xv = s_x[jg];             // broadcast within warp
            float4 a4 = cur[u];
            float v0 = adst4.x + aj, v1 = adst4.y + aj, v2 = adst4.z + aj, v3 = adst4.w + aj;
            float e0 = v0 > 0.f ? v0 : 0.2f * v0;
            float e1 = v1 > 0.f ? v1 : 0.2f * v1;
            float e2 = v2 > 0.f ? v2 : 0.2f * v2;
            float e3 = v3 > 0.f ? v3 : 0.2f * v3;
            bool m0 = (a4.x != 0.f) || (jg == i0 + pc + 0);
            bool m1 = (a4.y != 0.f) || (jg == i0 + pc + 1);
            bool m2 = (a4.z != 0.f) || (jg == i0 + pc + 2);
            bool m3 = (a4.w != 0.f) || (jg == i0 + pc + 3);
            float p0 = m0 ? __expf(e0) : 0.f;
            float p1 = m1 ? __expf(e1) : 0.f;
            float p2 = m2 ? __expf(e2) : 0.f;
            float p3 = m3 ? __expf(e3) : 0.f;
            den[0] += p0; den[1] += p1; den[2] += p2; den[3] += p3;
            accv[0].x += p0 * xv.x; accv[0].y += p0 * xv.y;
            accv[0].z += p0 * xv.z; accv[0].w += p0 * xv.w;
            accv[1].x += p1 * xv.x; accv[1].y += p1 * xv.y;
            accv[1].z += p1 * xv.z; accv[1].w += p1 * xv.w;
            accv[2].x += p2 * xv.x; accv[2].y += p2 * xv.y;
            accv[2].z += p2 * xv.z; accv[2].w += p2 * xv.w;
            accv[3].x += p3 * xv.x; accv[3].y += p3 * xv.y;
            accv[3].z += p3 * xv.z; accv[3].w += p3 * xv.w;
        }
    }

    // cross-warp (pj) reduction: stride-5 layout -> conflict-free
#pragma unroll
    for (int ii = 0; ii < 4; ii++) {
        s_red[pj][pc + ii][0] = accv[ii].x;
        s_red[pj][pc + ii][1] = accv[ii].y;
        s_red[pj][pc + ii][2] = accv[ii].z;
        s_red[pj][pc + ii][3] = accv[ii].w;
        s_red[pj][pc + ii][4] = den[ii];
    }
    __syncthreads();
    if (tid < TI) {
        float s0 = 0.f, s1 = 0.f, s2 = 0.f, s3 = 0.f, sd = 0.f;
#pragma unroll
        for (int k = 0; k < 8; k++) {
            s0 += s_red[k][tid][0];
            s1 += s_red[k][tid][1];
            s2 += s_red[k][tid][2];
            s3 += s_red[k][tid][3];
            sd += s_red[k][tid][4];
        }
        float rinv = 1.f / sd;
        *(float4*)&g_y[((size_t)bt * NN + i0 + tid) * 4] =
            make_float4(s0 * rinv, s1 * rinv, s2 * rinv, s3 * rinv);
    }
}

// ---------------- K4: GRU, 4 threads per sequence (one per hidden unit) ------
__global__ void k_gru(const float* __restrict__ Whh, const float* __restrict__ bhh) {
    __shared__ float sM[48], sW[48], sc[12], sb[12];
    int tid = threadIdx.x;
    if (tid < 48)       sM[tid]       = g_M[tid];
    else if (tid < 96)  sW[tid - 48]  = Whh[tid - 48];
    else if (tid < 108) sc[tid - 96]  = g_c[tid - 96];
    else if (tid < 120) sb[tid - 108] = bhh[tid - 108];
    __syncthreads();

    int gid = blockIdx.x * blockDim.x + tid;
    int q = gid >> 2;
    int f = gid & 3;
    if (q >= BB * NN) return;

    float M0[4], M1[4], M2[4], W0[4], W1[4], W2[4];
#pragma unroll
    for (int k = 0; k < 4; k++) {
        M0[k] = sM[f * 4 + k]; M1[k] = sM[(4 + f) * 4 + k]; M2[k] = sM[(8 + f) * 4 + k];
        W0[k] = sW[f * 4 + k]; W1[k] = sW[(4 + f) * 4 + k]; W2[k] = sW[(8 + f) * 4 + k];
    }
    float c0 = sc[f], c1 = sc[4 + f], c2 = sc[8 + f];
    float b0 = sb[f], b1 = sb[4 + f], b2 = sb[8 + f];

    float4 y[8];
#pragma unroll
    for (int s = 0; s < 8; s++)
        y[s] = *(const float4*)&g_y[(size_t)(q * 8 + s) * 4];

    int lane = tid & 31;
    int qb   = lane & ~3;
    float h = 0.f;
#pragma unroll
    for (int s = 0; s < 8; s++) {
        float gx0 = c0 + y[s].x * M0[0] + y[s].y * M0[1] + y[s].z * M0[2] + y[s].w * M0[3];
        float gx1 = c1 + y[s].x * M1[0] + y[s].y * M1[1] + y[s].z * M1[2] + y[s].w * M1[3];
        float gx2 = c2 + y[s].x * M2[0] + y[s].y * M2[1] + y[s].z * M2[2] + y[s].w * M2[3];
        float h0 = __shfl_sync(0xFFFFFFFFu, h, qb + 0);
        float h1 = __shfl_sync(0xFFFFFFFFu, h, qb + 1);
        float h2 = __shfl_sync(0xFFFFFFFFu, h, qb + 2);
        float h3 = __shfl_sync(0xFFFFFFFFu, h, qb + 3);
        float gh0 = b0 + h0 * W0[0] + h1 * W0[1] + h2 * W0[2] + h3 * W0[3];
        float gh1 = b1 + h0 * W1[0] + h1 * W1[1] + h2 * W1[2] + h3 * W1[3];
        float gh2 = b2 + h0 * W2[0] + h1 * W2[1] + h2 * W2[2] + h3 * W2[3];
        float r  = fsigmoid(gx0 + gh0);
        float z  = fsigmoid(gx1 + gh1);
        float nc = ftanh(gx2 + r * gh2);
        h = (1.f - z) * nc + z * h;
        g_gru[(size_t)(q * 8 + s) * 4 + f] = h;
    }
}

// ---------------- K5: Conv2d(8->12, 3x3, SAME over (N,4)) + Linear(4->2) -----
// grid (N/128, B, 6): each block does 2 output channels
__global__ void k_conv(const float* __restrict__ cW, const float* __restrict__ cb,
                       const float* __restrict__ oW, const float* __restrict__ ob,
                       float* __restrict__ out) {
    __shared__ float sg[130][33];
    __shared__ float sw[2 * TT * 9];
    __shared__ float sow[8], sob[2], scb[2];

    int b   = blockIdx.y;
    int n0  = blockIdx.x * 128;
    int co0 = blockIdx.z * 2;
    int tid = threadIdx.x;

    for (int i = tid; i < 2 * TT * 9; i += 128) sw[i] = cW[co0 * TT * 9 + i];
    if (tid < 8) sow[tid] = oW[tid];
    if (tid < 2) { sob[tid] = ob[tid]; scb[tid] = cb[co0 + tid]; }

    for (int i = tid; i < 130 * 32; i += 128) {
        int nl = i >> 5;
        int c  = i & 31;
        int n  = n0 + nl - 1;
        float v = 0.f;
        if (n >= 0 && n < NN)
            v = g_gru[(((size_t)b * NN + n) * TT) * FF + c];
        sg[nl][c] = v;
    }
    __syncthreads();

    int nl = tid;
#pragma unroll
    for (int cc = 0; cc < 2; cc++) {
        int co = co0 + cc;
        float y0 = scb[cc], y1 = scb[cc], y2 = scb[cc], y3 = scb[cc];
#pragma unroll
        for (int ci = 0; ci < TT; ci++) {
#pragma unroll
            for (int kh = 0; kh < 3; kh++) {
                const float* row = &sg[nl + kh][ci * 4];
                float r0 = row[0], r1 = row[1], r2 = row[2], r3 = row[3];
                const float* w = &sw[(cc * TT + ci) * 9 + kh * 3];
                float w0 = w[0], w1 = w[1], w2 = w[2];
                y0 += w1 * r0 + w2 * r1;
                y1 += w0 * r0 + w1 * r1 + w2 * r2;
                y2 += w0 * r1 + w1 * r2 + w2 * r3;
                y3 += w0 * r2 + w1 * r3;
            }
        }
        float o0 = sob[0] + y0 * sow[0] + y1 * sow[1] + y2 * sow[2] + y3 * sow[3];
        float o1 = sob[1] + y0 * sow[4] + y1 * sow[5] + y2 * sow[6] + y3 * sow[7];
        size_t oi = (((size_t)b * CCO + co) * NN + (n0 + nl)) * 2;
        out[oi]     = o0;
        out[oi + 1] = o1;
    }
}

// -----------------------------------------------------------------------------
extern "C" void kernel_launch(void* const* d_in, const int* in_sizes, int n_in,
                              void* d_out, int out_size) {
    const float* x        = (const float*)d_in[0];
    const float* adj      = (const float*)d_in[1];
    const float* gat_W    = (const float*)d_in[2];
    const float* att_src  = (const float*)d_in[3];
    const float* att_dst  = (const float*)d_in[4];
    const float* gat_bias = (const float*)d_in[5];
    const float* gru_Wih  = (const float*)d_in[6];
    const float* gru_Whh  = (const float*)d_in[7];
    const float* gru_bih  = (const float*)d_in[8];
    const float* gru_bhh  = (const float*)d_in[9];
    const float* conv_W   = (const float*)d_in[10];
    const float* conv_b   = (const float*)d_in[11];
    const float* out_W    = (const float*)d_in[12];
    const float* out_b    = (const float*)d_in[13];
    float* out = (float*)d_out;

    k_pre<<<(BB * TT * NN) / 256, 256>>>(x, gat_W, att_src, att_dst);
    k_mat<<<1, 64>>>(gru_Wih, gat_W, gat_bias, gru_bih);

    dim3 g2(NN / TI, BB * TT);
    k_att<<<g2, 256>>>(adj, x);

    k_gru<<<(BB * NN * 4) / 256, 256>>>(gru_Whh, gru_bhh);

    dim3 g5(NN / 128, BB, 6);
    k_conv<<<g5, 128>>>(conv_W, conv_b, out_W, out_b, out);
}